// round 3
// baseline (speedup 1.0000x reference)
#include <cuda_runtime.h>
#include <cstdint>

// Problem constants
#define BB 4
#define HW (512*1024)       // pixels per batch image
#define NI 8                // instances 1..8
#define NBINS 8192
#define WBIN (2.0f/(float)NBINS)
#define NTILE1 64
#define LAMBDA 0.72134752044448170f   // 0.5*log2(e)
#define INV1024 (1.0f/1024.0f)

// ---------------- device scratch ----------------
__device__ unsigned int g_hist[NI*BB*2*NBINS];     // 2 MB: [n][b][pos][bin]
__device__ float g_part[NI][BB][NTILE1][6];        // pass1 partials (cnt,e0,e1,q0,q1,qq)
__device__ float g_coef[BB][NI][8];                // a0,b0,a1,b1,k,cnt,sl,(pad)
__device__ float g_fg[BB][NI];
__device__ float g_bg[BB][2];
__device__ float g_lov[BB][NI];

// ---------------- fast tanh (Eigen-style rational, |err| ~1e-7) ----------------
__device__ __forceinline__ float tanh_fast(float x) {
    float xc = fminf(fmaxf(x, -7.99881172f), 7.99881172f);
    float x2 = xc * xc;
    float p = fmaf(x2, -2.76076847742355e-16f, 2.00018790482477e-13f);
    p = fmaf(x2, p, -8.60467152213735e-11f);
    p = fmaf(x2, p, 5.12229709037114e-08f);
    p = fmaf(x2, p, 1.48572235717979e-05f);
    p = fmaf(x2, p, 6.37261928875436e-04f);
    p = fmaf(x2, p, 4.89352455891786e-03f);
    p = p * xc;
    float q = fmaf(x2, 1.19825839466702e-06f, 1.18534705686654e-04f);
    q = fmaf(x2, q, 2.26843463243900e-03f);
    q = fmaf(x2, q, 4.89352518554385e-03f);
    return __fdividef(p, q);
}

// ---------------- pass 1: per (b, instance-group) masked sums + hist zero ----------------
#define P1_TPB 256
#define P1_PPT 32   // 8192 px/block -> 64 blocks/batch per group

__global__ __launch_bounds__(P1_TPB)
void pass1_kernel(const float* __restrict__ xv, const float* __restrict__ xs,
                  const int* __restrict__ t) {
    const int b = blockIdx.y;
    const int grp = blockIdx.z;              // instances 4*grp+1 .. 4*grp+4
    const int bx = blockIdx.x;
    const float* xv0 = xv + (long)b*2*HW;
    const float* xv1 = xv0 + HW;
    const float* xs0 = xs + (long)b*2*HW;
    const float* xs1 = xs0 + HW;
    const int*   tp  = t + (long)b*HW;

    float a[4][6];
    #pragma unroll
    for (int j = 0; j < 4; j++)
        #pragma unroll
        for (int i = 0; i < 6; i++) a[j][i] = 0.0f;

    const int p0 = bx * (P1_TPB * P1_PPT) + threadIdx.x;
    #pragma unroll 4
    for (int i = 0; i < P1_PPT; i++) {
        int p = p0 + i * P1_TPB;
        int tv = tp[p];
        unsigned rel = (unsigned)(tv - 1 - 4*grp);
        if (rel < 4u) {
            float e0 = tanh_fast(xv0[p]) + (float)(p >> 10) * INV1024;
            float e1 = tanh_fast(xv1[p]) + (float)(p & 1023) * INV1024;
            float q0 = xs0[p], q1 = xs1[p];
            float qq = q0*q0 + q1*q1;
            #pragma unroll
            for (int j = 0; j < 4; j++) {
                float m = (rel == (unsigned)j) ? 1.0f : 0.0f;
                a[j][0] += m;
                a[j][1] = fmaf(m, e0, a[j][1]);
                a[j][2] = fmaf(m, e1, a[j][2]);
                a[j][3] = fmaf(m, q0, a[j][3]);
                a[j][4] = fmaf(m, q1, a[j][4]);
                a[j][5] = fmaf(m, qq, a[j][5]);
            }
        }
    }
    // warp reduce 24 values
    #pragma unroll
    for (int off = 16; off; off >>= 1)
        #pragma unroll
        for (int j = 0; j < 4; j++)
            #pragma unroll
            for (int i = 0; i < 6; i++)
                a[j][i] += __shfl_down_sync(0xffffffffu, a[j][i], off);

    __shared__ float sacc[24];
    if (threadIdx.x < 24) sacc[threadIdx.x] = 0.0f;
    __syncthreads();
    if ((threadIdx.x & 31) == 0) {
        #pragma unroll
        for (int j = 0; j < 4; j++)
            #pragma unroll
            for (int i = 0; i < 6; i++)
                atomicAdd(&sacc[j*6+i], a[j][i]);
    }
    __syncthreads();
    if (threadIdx.x < 24)
        g_part[4*grp + threadIdx.x/6][b][bx][threadIdx.x % 6] = sacc[threadIdx.x];

    // zero histogram: 131072 threads total, 524288 words -> 4 each, coalesced
    int gid = (((int)blockIdx.z * BB + b) * NTILE1 + bx) * P1_TPB + threadIdx.x;
    g_hist[gid]          = 0u;
    g_hist[gid + 131072] = 0u;
    g_hist[gid + 262144] = 0u;
    g_hist[gid + 393216] = 0u;
}

// ---------------- finalize: reduce partials -> coefficients + sigma loss ----------------
__global__ __launch_bounds__(1024)
void finalize_kernel() {
    int tid = threadIdx.x;
    int w = tid >> 5, l = tid & 31;     // 32 warps = 32 (n,b) rows
    int n = w >> 2, b = w & 3;
    float s[6];
    #pragma unroll
    for (int i = 0; i < 6; i++)
        s[i] = g_part[n][b][l][i] + g_part[n][b][l + 32][i];
    #pragma unroll
    for (int off = 16; off; off >>= 1)
        #pragma unroll
        for (int i = 0; i < 6; i++)
            s[i] += __shfl_down_sync(0xffffffffu, s[i], off);
    if (l == 0) {
        float cnt = s[0];
        float inv = 1.0f / fmaxf(cnt, 1.0f);
        float c0 = s[1]*inv, c1 = s[2]*inv, pp0 = s[3]*inv, pp1 = s[4]*inv;
        float ps0 = expf(10.0f * pp0), ps1 = expf(10.0f * pp1);
        g_coef[b][n][0] = -LAMBDA * ps0;
        g_coef[b][n][1] = 2.0f * LAMBDA * ps0 * c0;
        g_coef[b][n][2] = -LAMBDA * ps1;
        g_coef[b][n][3] = 2.0f * LAMBDA * ps1 * c1;
        g_coef[b][n][4] = 13.0f - LAMBDA * (ps0*c0*c0 + ps1*c1*c1);
        g_coef[b][n][5] = cnt;
        // sigma loss closed form: (sum q^2)/safe - (cnt/safe)*(pp0^2+pp1^2)
        float sl = s[5]*inv - (cnt*inv) * (pp0*pp0 + pp1*pp1);
        g_coef[b][n][6] = fmaxf(sl, 0.0f);
    }
    if (tid < 32) ((float*)g_fg)[tid] = 0.0f;
    if (tid < 8)  ((float*)g_bg)[tid] = 0.0f;
}

// ---------------- pass 2: histograms + seed partials ----------------
#define P2_TPB 256
#define P2_PPT 8    // 2048 px/block -> 256 blocks/batch

__global__ __launch_bounds__(P2_TPB)
void pass2_kernel(const float* __restrict__ xv,
                  const float* __restrict__ xseed, const int* __restrict__ t) {
    const int b = blockIdx.y;
    const int tid = threadIdx.x;

    __shared__ float sa0[NI], sb0[NI], sa1[NI], sb1[NI], sk[NI];
    __shared__ float s_fg[NI];
    __shared__ float sbg[2];
    if (tid < NI) {
        sa0[tid] = g_coef[b][tid][0];
        sb0[tid] = g_coef[b][tid][1];
        sa1[tid] = g_coef[b][tid][2];
        sb1[tid] = g_coef[b][tid][3];
        sk[tid]  = g_coef[b][tid][4];
        s_fg[tid] = 0.0f;
    }
    if (tid < 2) sbg[tid] = 0.0f;
    __syncthreads();

    const float* xv0 = xv + (long)b*2*HW;
    const float* xv1 = xv0 + HW;
    const float* sdp = xseed + (long)b*HW;
    const int*   tp  = t + (long)b*HW;

    float bgc = 0.0f, bgs = 0.0f;
    float tfg[NI];
    #pragma unroll
    for (int n = 0; n < NI; n++) tfg[n] = 0.0f;

    const int p0 = blockIdx.x * (P2_TPB * P2_PPT) + tid;

    #pragma unroll 2
    for (int i = 0; i < P2_PPT; i++) {
        int p = p0 + i * P2_TPB;
        int tv = tp[p];
        float e0 = tanh_fast(xv0[p]) + (float)(p >> 10) * INV1024;
        float e1 = tanh_fast(xv1[p]) + (float)(p & 1023) * INV1024;
        float E0 = e0*e0, E1 = e1*e1;
        float sd = fmaf(tanh_fast(0.5f * sdp[p]), 0.5f, 0.5f);
        float isbg = (tv == 0) ? 1.0f : 0.0f;
        bgc += isbg;
        bgs = fmaf(isbg, sd*sd, bgs);

        #pragma unroll
        for (int n = 0; n < NI; n++) {
            // u = 13 - 0.5*log2e * dist   ->  y = 2^u = 8192 * gauss
            float u = fmaf(sa0[n], E0, fmaf(sb0[n], e0, fmaf(sa1[n], E1, fmaf(sb1[n], e1, sk[n]))));
            float um = fmaxf(u, -2.0f);
            float fr = um + 12582912.0f;           // round-to-nearest int
            float f  = um - (fr - 12582912.0f);    // f in [-0.5, 0.5]
            int   ib = __float_as_int(fr);
            float scale = __int_as_float((ib + (127 - 0x4B400000)) << 23); // 2^i
            float pe = fmaf(f, 1.33335581e-3f, 9.61812911e-3f);
            pe = fmaf(f, pe, 5.55041087e-2f);
            pe = fmaf(f, pe, 2.40226507e-1f);
            pe = fmaf(f, pe, 6.93147181e-1f);
            pe = fmaf(f, pe, 1.0f);
            float y = pe * scale;                  // = 8192*gauss
            bool pos = (tv == n + 1);
            float binf = pos ? (8192.0f - y) : y;  // err * BSCALE
            int bin = (int)binf;
            bin = min(bin, NBINS - 1);
            bin = max(bin, 0);
            int off = ((n*BB + b)*2 + (pos ? 1 : 0))*NBINS + bin;
            atomicAdd(&g_hist[off], 1u);
            if (pos) {
                float fgd = fmaf(y, -(1.0f/8192.0f), sd);
                tfg[n] = fmaf(fgd, fgd, tfg[n]);
            }
        }
    }

    // reduce bg + fg
    #pragma unroll
    for (int off = 16; off; off >>= 1) {
        bgc += __shfl_down_sync(0xffffffffu, bgc, off);
        bgs += __shfl_down_sync(0xffffffffu, bgs, off);
        #pragma unroll
        for (int n = 0; n < NI; n++)
            tfg[n] += __shfl_down_sync(0xffffffffu, tfg[n], off);
    }
    if ((tid & 31) == 0) {
        atomicAdd(&sbg[0], bgc);
        atomicAdd(&sbg[1], bgs);
        #pragma unroll
        for (int n = 0; n < NI; n++)
            atomicAdd(&s_fg[n], tfg[n]);
    }
    __syncthreads();
    if (tid < NI)
        atomicAdd(&g_fg[b][tid], s_fg[tid]);
    if (tid == NI)   atomicAdd(&g_bg[b][0], sbg[0]);
    if (tid == NI+1) atomicAdd(&g_bg[b][1], sbg[1]);
}

// ---------------- pass 3: histogram suffix scan -> lovasz ----------------
#define P3_TPB 1024
#define P3_BPT (NBINS / P3_TPB)   // 8 bins/thread

__global__ __launch_bounds__(P3_TPB)
void pass3_kernel() {
    const int row = blockIdx.x;    // 0..31
    const int n = row >> 2;
    const int b = row & 3;
    const uint4* hp4 = (const uint4*)(g_hist + (long)((n*BB + b)*2 + 1)*NBINS);
    const uint4* hn4 = (const uint4*)(g_hist + (long)((n*BB + b)*2 + 0)*NBINS);
    const int j = threadIdx.x;
    const int lane = j & 31;
    const int wrp = j >> 5;

    uint4 pa = hp4[2*j], pb = hp4[2*j + 1];
    uint4 na = hn4[2*j], nb = hn4[2*j + 1];
    float p[8] = {(float)pa.x,(float)pa.y,(float)pa.z,(float)pa.w,
                  (float)pb.x,(float)pb.y,(float)pb.z,(float)pb.w};
    float nn[8] = {(float)na.x,(float)na.y,(float)na.z,(float)na.w,
                   (float)nb.x,(float)nb.y,(float)nb.z,(float)nb.w};
    float tp = 0.0f, tn = 0.0f;
    #pragma unroll
    for (int k = 0; k < 8; k++) { tp += p[k]; tn += nn[k]; }

    // warp inclusive suffix scan (sum over lanes >= lane)
    float sp = tp, sn = tn;
    #pragma unroll
    for (int off = 1; off < 32; off <<= 1) {
        float a = __shfl_down_sync(0xffffffffu, sp, off);
        float c = __shfl_down_sync(0xffffffffu, sn, off);
        if (lane + off < 32) { sp += a; sn += c; }
    }
    __shared__ float swp[32], swn[32], sep[32], sen[32];
    __shared__ float sG, s_jacsum;
    if (lane == 0) { swp[wrp] = sp; swn[wrp] = sn; }
    if (j == 0) s_jacsum = 0.0f;
    __syncthreads();
    // warp 0: exclusive suffix over the 32 warp totals
    if (wrp == 0) {
        float wp = swp[lane], wn = swn[lane];
        float ip = wp, in_ = wn;
        #pragma unroll
        for (int off = 1; off < 32; off <<= 1) {
            float a = __shfl_down_sync(0xffffffffu, ip, off);
            float c = __shfl_down_sync(0xffffffffu, in_, off);
            if (lane + off < 32) { ip += a; in_ += c; }
        }
        sep[lane] = ip - wp;    // exclusive suffix (warps > lane)
        sen[lane] = in_ - wn;
        if (lane == 0) sG = ip; // total positives
    }
    __syncthreads();

    const float G = sG;
    float jacsum = 0.0f;
    if (G > 0.0f) {
        // thread-exclusive suffix = warps-after + lanes-after-within-warp
        float C = sep[wrp] + (sp - tp);
        float D = sen[wrp] + (sn - tn);
        #pragma unroll
        for (int k = 7; k >= 0; k--) {
            C += p[k];
            D += nn[k];
            float jac = 1.0f - __fdividef(G - C, G + D);
            if (j*8 + k >= 1) jacsum += jac;
        }
    }
    #pragma unroll
    for (int off = 16; off; off >>= 1)
        jacsum += __shfl_down_sync(0xffffffffu, jacsum, off);
    if (lane == 0) atomicAdd(&s_jacsum, jacsum);
    __syncthreads();
    if (j == 0)
        g_lov[b][n] = (G > 0.0f) ? WBIN * (0.5f + s_jacsum) : 0.0f;
}

// ---------------- final assembly ----------------
__global__ void final_kernel(float* __restrict__ out) {
    __shared__ float parts[BB];
    int b = threadIdx.x;
    if (b < BB) {
        float npres = 0.0f, lovs = 0.0f, sls = 0.0f, fgs = 0.0f;
        #pragma unroll
        for (int n = 0; n < NI; n++) {
            float cnt = g_coef[b][n][5];
            float pres = (cnt > 0.0f) ? 1.0f : 0.0f;
            float inv = 1.0f / fmaxf(cnt, 1.0f);
            npres += pres;
            lovs += pres * g_lov[b][n];
            sls  += pres * g_coef[b][n][6];
            fgs  += pres * g_fg[b][n] * inv;
        }
        float np = fmaxf(npres, 1.0f);
        float bgc = fmaxf(g_bg[b][0], 1.0f);
        float bgl = g_bg[b][1] / bgc;
        parts[b] = lovs / np + sls / np + (bgl + fgs) / (1.0f + npres);
    }
    __syncthreads();
    if (threadIdx.x == 0)
        out[0] = (parts[0] + parts[1] + parts[2] + parts[3]) * 0.25f;
}

// ---------------- launch ----------------
extern "C" void kernel_launch(void* const* d_in, const int* in_sizes, int n_in,
                              void* d_out, int out_size) {
    const float* xv    = (const float*)d_in[0];   // [4,2,512,1024]
    const float* xs    = (const float*)d_in[1];   // [4,2,512,1024]
    const float* xseed = (const float*)d_in[2];   // [4,1,512,1024]
    const int*   t     = (const int*)d_in[3];     // [4,512,1024]
    float* out = (float*)d_out;

    dim3 g1(NTILE1, BB, 2);
    pass1_kernel<<<g1, P1_TPB>>>(xv, xs, t);

    finalize_kernel<<<1, 1024>>>();

    dim3 g2(HW / (P2_TPB * P2_PPT), BB);   // (256, 4)
    pass2_kernel<<<g2, P2_TPB>>>(xv, xseed, t);

    pass3_kernel<<<NI * BB, P3_TPB>>>();

    final_kernel<<<1, 32>>>(out);
}

// round 4
// speedup vs baseline: 1.3986x; 1.3986x over previous
#include <cuda_runtime.h>
#include <cstdint>

// Problem constants
#define BB 4
#define HW (512*1024)       // pixels per batch image
#define NI 8                // instances 1..8
#define NBINS 8192
#define WBIN (2.0f/(float)NBINS)
#define NTILE1 64
#define LAMBDA 0.72134752044448170f   // 0.5*log2(e)
#define INV1024 (1.0f/1024.0f)

// ---------------- device scratch ----------------
__device__ unsigned int g_hist[NI*BB*2*NBINS];     // 2 MB: [n][b][pos][bin]
__device__ float g_part[NI][BB][NTILE1][6];        // pass1 partials (cnt,e0,e1,q0,q1,qq)
__device__ float g_coef[BB][NI][8];                // a0,b0,a1,b1,k,cnt,sl,(pad)
__device__ float g_fg[BB][NI];
__device__ float g_bg[BB][2];
__device__ float g_lov[BB][NI];

// ---------------- fast tanh (Eigen-style rational, |err| ~1e-7) ----------------
__device__ __forceinline__ float tanh_fast(float x) {
    float xc = fminf(fmaxf(x, -7.99881172f), 7.99881172f);
    float x2 = xc * xc;
    float p = fmaf(x2, -2.76076847742355e-16f, 2.00018790482477e-13f);
    p = fmaf(x2, p, -8.60467152213735e-11f);
    p = fmaf(x2, p, 5.12229709037114e-08f);
    p = fmaf(x2, p, 1.48572235717979e-05f);
    p = fmaf(x2, p, 6.37261928875436e-04f);
    p = fmaf(x2, p, 4.89352455891786e-03f);
    p = p * xc;
    float q = fmaf(x2, 1.19825839466702e-06f, 1.18534705686654e-04f);
    q = fmaf(x2, q, 2.26843463243900e-03f);
    q = fmaf(x2, q, 4.89352518554385e-03f);
    return __fdividef(p, q);
}

// ---------------- pass 1: per (b, instance-group) masked sums + hist zero ----------------
#define P1_TPB 256
#define P1_PPT 32   // 8192 px/block -> 64 blocks/batch per group

__global__ __launch_bounds__(P1_TPB)
void pass1_kernel(const float* __restrict__ xv, const float* __restrict__ xs,
                  const int* __restrict__ t) {
    const int b = blockIdx.y;
    const int grp = blockIdx.z;              // instances 4*grp+1 .. 4*grp+4
    const int bx = blockIdx.x;
    const float* xv0 = xv + (long)b*2*HW;
    const float* xv1 = xv0 + HW;
    const float* xs0 = xs + (long)b*2*HW;
    const float* xs1 = xs0 + HW;
    const int*   tp  = t + (long)b*HW;

    float a[4][6];
    #pragma unroll
    for (int j = 0; j < 4; j++)
        #pragma unroll
        for (int i = 0; i < 6; i++) a[j][i] = 0.0f;

    const int p0 = bx * (P1_TPB * P1_PPT) + threadIdx.x;
    #pragma unroll 4
    for (int i = 0; i < P1_PPT; i++) {
        int p = p0 + i * P1_TPB;
        int tv = tp[p];
        unsigned rel = (unsigned)(tv - 1 - 4*grp);
        if (rel < 4u) {
            float e0 = tanh_fast(xv0[p]) + (float)(p >> 10) * INV1024;
            float e1 = tanh_fast(xv1[p]) + (float)(p & 1023) * INV1024;
            float q0 = xs0[p], q1 = xs1[p];
            float qq = q0*q0 + q1*q1;
            #pragma unroll
            for (int j = 0; j < 4; j++) {
                float m = (rel == (unsigned)j) ? 1.0f : 0.0f;
                a[j][0] += m;
                a[j][1] = fmaf(m, e0, a[j][1]);
                a[j][2] = fmaf(m, e1, a[j][2]);
                a[j][3] = fmaf(m, q0, a[j][3]);
                a[j][4] = fmaf(m, q1, a[j][4]);
                a[j][5] = fmaf(m, qq, a[j][5]);
            }
        }
    }
    // warp reduce 24 values
    #pragma unroll
    for (int off = 16; off; off >>= 1)
        #pragma unroll
        for (int j = 0; j < 4; j++)
            #pragma unroll
            for (int i = 0; i < 6; i++)
                a[j][i] += __shfl_down_sync(0xffffffffu, a[j][i], off);

    __shared__ float sacc[24];
    if (threadIdx.x < 24) sacc[threadIdx.x] = 0.0f;
    __syncthreads();
    if ((threadIdx.x & 31) == 0) {
        #pragma unroll
        for (int j = 0; j < 4; j++)
            #pragma unroll
            for (int i = 0; i < 6; i++)
                atomicAdd(&sacc[j*6+i], a[j][i]);
    }
    __syncthreads();
    if (threadIdx.x < 24)
        g_part[4*grp + threadIdx.x/6][b][bx][threadIdx.x % 6] = sacc[threadIdx.x];

    // zero histogram: 131072 threads total, 524288 words -> 4 each, coalesced
    int gid = (((int)blockIdx.z * BB + b) * NTILE1 + bx) * P1_TPB + threadIdx.x;
    g_hist[gid]          = 0u;
    g_hist[gid + 131072] = 0u;
    g_hist[gid + 262144] = 0u;
    g_hist[gid + 393216] = 0u;
}

// ---------------- finalize: reduce partials -> coefficients + sigma loss ----------------
__global__ __launch_bounds__(1024)
void finalize_kernel() {
    int tid = threadIdx.x;
    int w = tid >> 5, l = tid & 31;     // 32 warps = 32 (n,b) rows
    int n = w >> 2, b = w & 3;
    float s[6];
    #pragma unroll
    for (int i = 0; i < 6; i++)
        s[i] = g_part[n][b][l][i] + g_part[n][b][l + 32][i];
    #pragma unroll
    for (int off = 16; off; off >>= 1)
        #pragma unroll
        for (int i = 0; i < 6; i++)
            s[i] += __shfl_down_sync(0xffffffffu, s[i], off);
    if (l == 0) {
        float cnt = s[0];
        float inv = 1.0f / fmaxf(cnt, 1.0f);
        float c0 = s[1]*inv, c1 = s[2]*inv, pp0 = s[3]*inv, pp1 = s[4]*inv;
        float ps0 = expf(10.0f * pp0), ps1 = expf(10.0f * pp1);
        g_coef[b][n][0] = -LAMBDA * ps0;
        g_coef[b][n][1] = 2.0f * LAMBDA * ps0 * c0;
        g_coef[b][n][2] = -LAMBDA * ps1;
        g_coef[b][n][3] = 2.0f * LAMBDA * ps1 * c1;
        g_coef[b][n][4] = 13.0f - LAMBDA * (ps0*c0*c0 + ps1*c1*c1);
        g_coef[b][n][5] = cnt;
        // sigma loss closed form: (sum q^2)/safe - (cnt/safe)*(pp0^2+pp1^2)
        float sl = s[5]*inv - (cnt*inv) * (pp0*pp0 + pp1*pp1);
        g_coef[b][n][6] = fmaxf(sl, 0.0f);
    }
    if (tid < 32) ((float*)g_fg)[tid] = 0.0f;
    if (tid < 8)  ((float*)g_bg)[tid] = 0.0f;
}

// ---------------- pass 2: histograms + seed partials (round-2 structure) ----------------
#define P2_TPB 256
#define P2_PPT 8    // 2048 px/block -> 256 blocks/batch

__global__ __launch_bounds__(P2_TPB)
void pass2_kernel(const float* __restrict__ xv,
                  const float* __restrict__ xseed, const int* __restrict__ t) {
    const int b = blockIdx.y;
    const int tid = threadIdx.x;
    const int wid = tid >> 5;

    __shared__ float sa0[NI], sb0[NI], sa1[NI], sb1[NI], sk[NI];
    __shared__ float s_fg[8][NI+1];
    __shared__ float sbg[2];
    if (tid < NI) {
        sa0[tid] = g_coef[b][tid][0];
        sb0[tid] = g_coef[b][tid][1];
        sa1[tid] = g_coef[b][tid][2];
        sb1[tid] = g_coef[b][tid][3];
        sk[tid]  = g_coef[b][tid][4];
    }
    if (tid < 8*(NI+1)) ((float*)s_fg)[tid] = 0.0f;
    if (tid < 2) sbg[tid] = 0.0f;
    __syncthreads();

    const float* xv0 = xv + (long)b*2*HW;
    const float* xv1 = xv0 + HW;
    const float* sdp = xseed + (long)b*HW;
    const int*   tp  = t + (long)b*HW;

    float bgc = 0.0f, bgs = 0.0f;
    const int p0 = blockIdx.x * (P2_TPB * P2_PPT) + tid;

    for (int i = 0; i < P2_PPT; i++) {
        int p = p0 + i * P2_TPB;
        int tv = tp[p];
        float e0 = tanh_fast(xv0[p]) + (float)(p >> 10) * INV1024;
        float e1 = tanh_fast(xv1[p]) + (float)(p & 1023) * INV1024;
        float E0 = e0*e0, E1 = e1*e1;
        float sd = fmaf(tanh_fast(0.5f * sdp[p]), 0.5f, 0.5f);
        float isbg = (tv == 0) ? 1.0f : 0.0f;
        bgc += isbg;
        bgs = fmaf(isbg, sd*sd, bgs);

        float yown = 0.0f;
        #pragma unroll
        for (int n = 0; n < NI; n++) {
            // u = 13 - 0.5*log2e * dist   ->  y = 2^u = 8192 * gauss
            float u = fmaf(sa0[n], E0, fmaf(sb0[n], e0, fmaf(sa1[n], E1, fmaf(sb1[n], e1, sk[n]))));
            float um = fmaxf(u, -2.0f);
            float fr = um + 12582912.0f;           // round-to-nearest int
            float f  = um - (fr - 12582912.0f);    // f in [-0.5, 0.5]
            int   ib = __float_as_int(fr);
            float scale = __int_as_float((ib + (127 - 0x4B400000)) << 23); // 2^i
            float pe = fmaf(f, 1.33335581e-3f, 9.61812911e-3f);
            pe = fmaf(f, pe, 5.55041087e-2f);
            pe = fmaf(f, pe, 2.40226507e-1f);
            pe = fmaf(f, pe, 6.93147181e-1f);
            pe = fmaf(f, pe, 1.0f);
            float y = pe * scale;                  // = 8192*gauss
            bool pos = (tv == n + 1);
            if (pos) yown = y;
            float binf = pos ? (8192.0f - y) : y;  // err * BSCALE
            int bin = (int)binf;
            bin = min(bin, NBINS - 1);
            bin = max(bin, 0);
            int off = ((n*BB + b)*2 + (pos ? 1 : 0))*NBINS + bin;
            atomicAdd(&g_hist[off], 1u);
        }
        // own-instance seed fg term via tv-indexed smem atomic
        float fgd = fmaf(yown, -(1.0f/8192.0f), sd);
        if (tv > 0)
            atomicAdd(&s_fg[wid][tv], fgd * fgd);
    }
    __syncthreads();

    // bg reduce
    #pragma unroll
    for (int off = 16; off; off >>= 1) {
        bgc += __shfl_down_sync(0xffffffffu, bgc, off);
        bgs += __shfl_down_sync(0xffffffffu, bgs, off);
    }
    if ((tid & 31) == 0) {
        atomicAdd(&sbg[0], bgc);
        atomicAdd(&sbg[1], bgs);
    }
    // fg block reduce -> global
    if (tid >= 32 && tid < 32 + NI) {
        int n = tid - 32;
        float sfg = 0.0f;
        #pragma unroll
        for (int w = 0; w < 8; w++) sfg += s_fg[w][n+1];
        atomicAdd(&g_fg[b][n], sfg);
    }
    __syncthreads();
    if (tid == 0) {
        atomicAdd(&g_bg[b][0], sbg[0]);
        atomicAdd(&g_bg[b][1], sbg[1]);
    }
}

// ---------------- pass 3: histogram suffix scan -> lovasz ----------------
#define P3_TPB 1024
#define P3_BPT (NBINS / P3_TPB)   // 8 bins/thread

__global__ __launch_bounds__(P3_TPB)
void pass3_kernel() {
    const int row = blockIdx.x;    // 0..31
    const int n = row >> 2;
    const int b = row & 3;
    const uint4* hp4 = (const uint4*)(g_hist + (long)((n*BB + b)*2 + 1)*NBINS);
    const uint4* hn4 = (const uint4*)(g_hist + (long)((n*BB + b)*2 + 0)*NBINS);
    const int j = threadIdx.x;
    const int lane = j & 31;
    const int wrp = j >> 5;

    uint4 pa = hp4[2*j], pb = hp4[2*j + 1];
    uint4 na = hn4[2*j], nb = hn4[2*j + 1];
    float p[8] = {(float)pa.x,(float)pa.y,(float)pa.z,(float)pa.w,
                  (float)pb.x,(float)pb.y,(float)pb.z,(float)pb.w};
    float nn[8] = {(float)na.x,(float)na.y,(float)na.z,(float)na.w,
                   (float)nb.x,(float)nb.y,(float)nb.z,(float)nb.w};
    float tp = 0.0f, tn = 0.0f;
    #pragma unroll
    for (int k = 0; k < 8; k++) { tp += p[k]; tn += nn[k]; }

    // warp inclusive suffix scan (sum over lanes >= lane)
    float sp = tp, sn = tn;
    #pragma unroll
    for (int off = 1; off < 32; off <<= 1) {
        float a = __shfl_down_sync(0xffffffffu, sp, off);
        float c = __shfl_down_sync(0xffffffffu, sn, off);
        if (lane + off < 32) { sp += a; sn += c; }
    }
    __shared__ float swp[32], swn[32], sep[32], sen[32];
    __shared__ float sG, s_jacsum;
    if (lane == 0) { swp[wrp] = sp; swn[wrp] = sn; }
    if (j == 0) s_jacsum = 0.0f;
    __syncthreads();
    // warp 0: exclusive suffix over the 32 warp totals
    if (wrp == 0) {
        float wp = swp[lane], wn = swn[lane];
        float ip = wp, in_ = wn;
        #pragma unroll
        for (int off = 1; off < 32; off <<= 1) {
            float a = __shfl_down_sync(0xffffffffu, ip, off);
            float c = __shfl_down_sync(0xffffffffu, in_, off);
            if (lane + off < 32) { ip += a; in_ += c; }
        }
        sep[lane] = ip - wp;    // exclusive suffix (warps > lane)
        sen[lane] = in_ - wn;
        if (lane == 0) sG = ip; // total positives
    }
    __syncthreads();

    const float G = sG;
    float jacsum = 0.0f;
    if (G > 0.0f) {
        // thread-exclusive suffix = warps-after + lanes-after-within-warp
        float C = sep[wrp] + (sp - tp);
        float D = sen[wrp] + (sn - tn);
        #pragma unroll
        for (int k = 7; k >= 0; k--) {
            C += p[k];
            D += nn[k];
            float jac = 1.0f - __fdividef(G - C, G + D);
            if (j*8 + k >= 1) jacsum += jac;
        }
    }
    #pragma unroll
    for (int off = 16; off; off >>= 1)
        jacsum += __shfl_down_sync(0xffffffffu, jacsum, off);
    if (lane == 0) atomicAdd(&s_jacsum, jacsum);
    __syncthreads();
    if (j == 0)
        g_lov[b][n] = (G > 0.0f) ? WBIN * (0.5f + s_jacsum) : 0.0f;
}

// ---------------- final assembly ----------------
__global__ void final_kernel(float* __restrict__ out) {
    __shared__ float parts[BB];
    int b = threadIdx.x;
    if (b < BB) {
        float npres = 0.0f, lovs = 0.0f, sls = 0.0f, fgs = 0.0f;
        #pragma unroll
        for (int n = 0; n < NI; n++) {
            float cnt = g_coef[b][n][5];
            float pres = (cnt > 0.0f) ? 1.0f : 0.0f;
            float inv = 1.0f / fmaxf(cnt, 1.0f);
            npres += pres;
            lovs += pres * g_lov[b][n];
            sls  += pres * g_coef[b][n][6];
            fgs  += pres * g_fg[b][n] * inv;
        }
        float np = fmaxf(npres, 1.0f);
        float bgc = fmaxf(g_bg[b][0], 1.0f);
        float bgl = g_bg[b][1] / bgc;
        parts[b] = lovs / np + sls / np + (bgl + fgs) / (1.0f + npres);
    }
    __syncthreads();
    if (threadIdx.x == 0)
        out[0] = (parts[0] + parts[1] + parts[2] + parts[3]) * 0.25f;
}

// ---------------- launch ----------------
extern "C" void kernel_launch(void* const* d_in, const int* in_sizes, int n_in,
                              void* d_out, int out_size) {
    const float* xv    = (const float*)d_in[0];   // [4,2,512,1024]
    const float* xs    = (const float*)d_in[1];   // [4,2,512,1024]
    const float* xseed = (const float*)d_in[2];   // [4,1,512,1024]
    const int*   t     = (const int*)d_in[3];     // [4,512,1024]
    float* out = (float*)d_out;

    dim3 g1(NTILE1, BB, 2);
    pass1_kernel<<<g1, P1_TPB>>>(xv, xs, t);

    finalize_kernel<<<1, 1024>>>();

    dim3 g2(HW / (P2_TPB * P2_PPT), BB);   // (256, 4)
    pass2_kernel<<<g2, P2_TPB>>>(xv, xseed, t);

    pass3_kernel<<<NI * BB, P3_TPB>>>();

    final_kernel<<<1, 32>>>(out);
}